// round 3
// baseline (speedup 1.0000x reference)
#include <cuda_runtime.h>
#include <cfloat>
#include <cstdint>

#define N_NODES 50000
#define IN_DIM  1024
#define E_EDGES 100000
#define NUM_REL 40
#define HEADS   4
#define OUT_DIM 200
#define HID     800
#define BATCH   8192
#define NEG_SLOPE 0.2f

// ---------------- scratch (device globals; no allocation allowed) ----------------
__device__ __align__(16) float g_h  [(size_t)N_NODES * HID];   // node_emb @ W
__device__ __align__(16) float g_out[(size_t)N_NODES * HID];   // aggregated output
__device__ float g_ssrc  [N_NODES * HEADS];
__device__ float g_sdst  [N_NODES * HEADS];
__device__ float g_rlog  [NUM_REL * HEADS];
__device__ float g_segmax[N_NODES * HEADS];
__device__ float g_denom [N_NODES * HEADS];
__device__ float g_elog  [E_EDGES * HEADS];
__device__ int   g_is64;   // 1 if index arrays are int64, 0 if int32

// ---------------- helpers ----------------
__device__ __forceinline__ int load_idx(const void* p, int i) {
    if (g_is64) return (int)((const long long*)p)[i];
    return ((const int*)p)[i];
}

__device__ __forceinline__ void atomicMaxFloat(float* addr, float val) {
    if (val >= 0.0f) atomicMax((int*)addr, __float_as_int(val));
    else             atomicMin((unsigned int*)addr, __float_as_uint(val));
}

__device__ __forceinline__ float warp_reduce(float v) {
    #pragma unroll
    for (int o = 16; o > 0; o >>= 1) v += __shfl_down_sync(0xffffffffu, v, o);
    return v;
}

// ---------------- 0) dtype detection ----------------
// If the first 64 entries interpreted as int64 all land in [0, N_NODES), the
// data is int64. For int32 data, each interpreted value is lo + hi*2^32 where
// hi is a neighboring random index in [0,50000) — at least one is out of range
// with probability ~1.
__global__ void detect_dtype_kernel(const void* edge_index) {
    if (threadIdx.x == 0 && blockIdx.x == 0) {
        const long long* p = (const long long*)edge_index;
        int ok = 1;
        for (int i = 0; i < 64; i++) {
            long long v = p[i];
            if (v < 0 || v >= N_NODES) { ok = 0; break; }
        }
        g_is64 = ok;
    }
}

// ---------------- 1) GEMM: g_h = node_emb[50000,1024] @ W[1024,800] ----------------
// BM=128, BN=64, BK=16, 256 threads, each computes 8x4.
__global__ void __launch_bounds__(256) gemm_kernel(const float* __restrict__ A,
                                                   const float* __restrict__ Wm) {
    const int t  = threadIdx.x;
    const int tx = t & 15;          // 0..15 -> 4 cols each
    const int ty = t >> 4;          // 0..15 -> 8 rows each
    const int row0 = blockIdx.x * 128;
    const int col0 = blockIdx.y * 64;

    __shared__ float As[16][128];
    __shared__ float Bs[16][64];

    float acc[8][4];
    #pragma unroll
    for (int i = 0; i < 8; i++)
        #pragma unroll
        for (int j = 0; j < 4; j++) acc[i][j] = 0.0f;

    for (int k0 = 0; k0 < IN_DIM; k0 += 16) {
        // load A tile: 128 rows x 16 k = 512 float4 slots
        #pragma unroll
        for (int i = 0; i < 2; i++) {
            int s  = t + 256 * i;        // 0..511
            int r  = s >> 2;             // row within tile
            int kq = (s & 3) * 4;        // k-offset (0,4,8,12)
            float4 v = make_float4(0.f, 0.f, 0.f, 0.f);
            int gr = row0 + r;
            if (gr < N_NODES)
                v = *(const float4*)(A + (size_t)gr * IN_DIM + k0 + kq);
            As[kq + 0][r] = v.x; As[kq + 1][r] = v.y;
            As[kq + 2][r] = v.z; As[kq + 3][r] = v.w;
        }
        // load B tile: 16 k x 64 cols = 256 float4 slots
        {
            int kr = t >> 4;             // 0..15
            int cq = (t & 15) * 4;       // 0..60
            float4 v = make_float4(0.f, 0.f, 0.f, 0.f);
            int gc = col0 + cq;
            if (gc < HID)
                v = *(const float4*)(Wm + (size_t)(k0 + kr) * HID + gc);
            Bs[kr][cq + 0] = v.x; Bs[kr][cq + 1] = v.y;
            Bs[kr][cq + 2] = v.z; Bs[kr][cq + 3] = v.w;
        }
        __syncthreads();

        #pragma unroll
        for (int kk = 0; kk < 16; kk++) {
            float a[8], b[4];
            #pragma unroll
            for (int i = 0; i < 8; i++) a[i] = As[kk][ty * 8 + i];
            #pragma unroll
            for (int j = 0; j < 4; j++) b[j] = Bs[kk][tx * 4 + j];
            #pragma unroll
            for (int i = 0; i < 8; i++)
                #pragma unroll
                for (int j = 0; j < 4; j++) acc[i][j] = fmaf(a[i], b[j], acc[i][j]);
        }
        __syncthreads();
    }

    const int gc = col0 + tx * 4;
    if (gc < HID) {
        #pragma unroll
        for (int i = 0; i < 8; i++) {
            int gr = row0 + ty * 8 + i;
            if (gr < N_NODES) {
                float4 v = make_float4(acc[i][0], acc[i][1], acc[i][2], acc[i][3]);
                *(float4*)(g_h + (size_t)gr * HID + gc) = v;
            }
        }
    }
}

// ---------------- 2) init: out=0, segmax=-inf, denom=0 ----------------
__global__ void init_kernel() {
    const size_t tid = (size_t)blockIdx.x * blockDim.x + threadIdx.x;
    const size_t nthreads = (size_t)gridDim.x * blockDim.x;
    float4* o4 = (float4*)g_out;
    const size_t tot4 = (size_t)N_NODES * HID / 4;
    for (size_t i = tid; i < tot4; i += nthreads)
        o4[i] = make_float4(0.f, 0.f, 0.f, 0.f);
    if (tid < (size_t)N_NODES * HEADS) {
        g_segmax[tid] = -FLT_MAX;
        g_denom[tid]  = 0.0f;
    }
}

// ---------------- 3) per-node attention projections ----------------
__global__ void node_logits_kernel(const float* __restrict__ a_src,
                                   const float* __restrict__ a_dst) {
    int wid  = (blockIdx.x * blockDim.x + threadIdx.x) >> 5;
    int lane = threadIdx.x & 31;
    if (wid >= N_NODES * HEADS) return;
    int n = wid >> 2, h = wid & 3;
    const float* hp = g_h + (size_t)n * HID + h * OUT_DIM;
    const float* as = a_src + h * OUT_DIM;
    const float* ad = a_dst + h * OUT_DIM;
    float ss = 0.f, sd = 0.f;
    for (int d = lane; d < OUT_DIM; d += 32) {
        float v = hp[d];
        ss = fmaf(v, as[d], ss);
        sd = fmaf(v, ad[d], sd);
    }
    ss = warp_reduce(ss);
    sd = warp_reduce(sd);
    if (lane == 0) { g_ssrc[wid] = ss; g_sdst[wid] = sd; }
}

__global__ void rel_logits_kernel(const float* __restrict__ rel_feat,
                                  const float* __restrict__ a_rel) {
    int wid  = (blockIdx.x * blockDim.x + threadIdx.x) >> 5;
    int lane = threadIdx.x & 31;
    if (wid >= NUM_REL * HEADS) return;
    int r = wid >> 2, h = wid & 3;
    const float* rp = rel_feat + (size_t)r * HID + h * OUT_DIM;
    const float* ar = a_rel + h * OUT_DIM;
    float s = 0.f;
    for (int d = lane; d < OUT_DIM; d += 32) s = fmaf(rp[d], ar[d], s);
    s = warp_reduce(s);
    if (lane == 0) g_rlog[wid] = s;
}

// ---------------- 4) per-edge logits + segment max ----------------
__global__ void edge_max_kernel(const void* __restrict__ ei,
                                const void* __restrict__ et) {
    int idx = blockIdx.x * blockDim.x + threadIdx.x;
    if (idx >= E_EDGES * HEADS) return;
    int e = idx >> 2, h = idx & 3;
    int s = load_idx(ei, e);
    int d = load_idx(ei, E_EDGES + e);
    int r = load_idx(et, e);
    float x = g_ssrc[s * 4 + h] + g_sdst[d * 4 + h] + g_rlog[r * 4 + h];
    x = (x >= 0.f) ? x : NEG_SLOPE * x;
    g_elog[idx] = x;
    atomicMaxFloat(&g_segmax[d * 4 + h], x);
}

// ---------------- 5) exp + segment sum ----------------
__global__ void edge_exp_kernel(const void* __restrict__ ei) {
    int idx = blockIdx.x * blockDim.x + threadIdx.x;
    if (idx >= E_EDGES * HEADS) return;
    int e = idx >> 2, h = idx & 3;
    int d = load_idx(ei, E_EDGES + e);
    float ev = expf(g_elog[idx] - g_segmax[d * 4 + h]);
    g_elog[idx] = ev;
    atomicAdd(&g_denom[d * 4 + h], ev);
}

// ---------------- 6) weighted scatter-aggregate: out[dst] += alpha * h[src] --------
__global__ void edge_agg_kernel(const void* __restrict__ ei) {
    int wid  = (blockIdx.x * blockDim.x + threadIdx.x) >> 5;
    int lane = threadIdx.x & 31;
    if (wid >= E_EDGES) return;
    int s = load_idx(ei, wid);
    int d = load_idx(ei, E_EDGES + wid);
    float alpha[HEADS];
    #pragma unroll
    for (int h = 0; h < HEADS; h++)
        alpha[h] = g_elog[wid * 4 + h] / g_denom[d * 4 + h];
    const float4* hs = (const float4*)(g_h + (size_t)s * HID);
    float4*       op = (float4*)(g_out + (size_t)d * HID);
    for (int c = lane; c < HID / 4; c += 32) {   // 200 float4 chunks; head = c/50
        float a = alpha[c / 50];
        float4 v = hs[c];
        float4 w = make_float4(v.x * a, v.y * a, v.z * a, v.w * a);
        atomicAdd(op + c, w);                    // vector RED, sm_90+
    }
}

// ---------------- 7) DistMult scoring ----------------
__global__ void distmult_kernel(const float* __restrict__ bias,
                                const float* __restrict__ rel_emb,
                                const void* __restrict__ si,
                                const void* __restrict__ ri,
                                const void* __restrict__ di,
                                float* __restrict__ out) {
    int wid  = (blockIdx.x * blockDim.x + threadIdx.x) >> 5;
    int lane = threadIdx.x & 31;
    if (wid >= BATCH) return;
    int s = load_idx(si, wid);
    int r = load_idx(ri, wid);
    int d = load_idx(di, wid);
    const float* ps = g_out + (size_t)s * HID;
    const float* pd = g_out + (size_t)d * HID;
    const float* pr = rel_emb + (size_t)r * HID;
    float acc = 0.f;
    for (int k = lane; k < HID; k += 32) {
        float b = bias[k];
        acc = fmaf((ps[k] + b) * pr[k], (pd[k] + b), acc);
    }
    acc = warp_reduce(acc);
    if (lane == 0) out[wid] = acc;
}

// ---------------- launch ----------------
extern "C" void kernel_launch(void* const* d_in, const int* in_sizes, int n_in,
                              void* d_out, int out_size) {
    const float* node_emb   = (const float*)d_in[0];
    const float* Wm         = (const float*)d_in[1];
    const float* bias       = (const float*)d_in[2];
    const float* a_src      = (const float*)d_in[3];
    const float* a_dst      = (const float*)d_in[4];
    const float* a_rel      = (const float*)d_in[5];
    const float* rel_feat   = (const float*)d_in[6];
    const float* rel_emb    = (const float*)d_in[7];
    const void*  edge_index = d_in[8];
    const void*  edge_type  = d_in[9];
    const void*  src_ids    = d_in[10];
    const void*  rel_ids    = d_in[11];
    const void*  dst_ids    = d_in[12];
    float* out = (float*)d_out;

    detect_dtype_kernel<<<1, 32>>>(edge_index);

    dim3 gemm_grid((N_NODES + 127) / 128, (HID + 63) / 64);
    gemm_kernel<<<gemm_grid, 256>>>(node_emb, Wm);

    init_kernel<<<(N_NODES * HEADS + 255) / 256, 256>>>();

    node_logits_kernel<<<(N_NODES * HEADS * 32 + 255) / 256, 256>>>(a_src, a_dst);
    rel_logits_kernel<<<(NUM_REL * HEADS * 32 + 255) / 256, 256>>>(rel_feat, a_rel);

    edge_max_kernel<<<(E_EDGES * HEADS + 255) / 256, 256>>>(edge_index, edge_type);
    edge_exp_kernel<<<(E_EDGES * HEADS + 255) / 256, 256>>>(edge_index);
    edge_agg_kernel<<<(E_EDGES * 32 + 255) / 256, 256>>>(edge_index);

    distmult_kernel<<<(BATCH * 32 + 255) / 256, 256>>>(bias, rel_emb,
                                                       src_ids, rel_ids, dst_ids, out);
}

// round 5
// speedup vs baseline: 2.0089x; 2.0089x over previous
#include <cuda_runtime.h>
#include <cuda_bf16.h>
#include <cfloat>
#include <cstdint>

#define N_NODES 50000
#define IN_DIM  1024
#define E_EDGES 100000
#define NUM_REL 40
#define HEADS   4
#define OUT_DIM 200
#define HID     800
#define BATCH   8192
#define NEG_SLOPE 0.2f

#define BM 128
#define BN 64
#define BK 32
#define NCHUNK (IN_DIM / BK)            // 32
#define NT_M ((N_NODES + BM - 1) / BM)  // 391
#define NT_N 13                         // ceil(800/64)
#define PAD_N (NT_N * BN)               // 832

// smem layout (bytes from dynamic base); padded row stride 80B (40 bf16)
#define A_STRIDE 80
#define A_VER_SZ (128 * A_STRIDE)       // 10240
#define B_VER_SZ (64 * A_STRIDE)        // 5120
#define SA_OFF(buf, ver) ((buf) * (2 * A_VER_SZ) + (ver) * A_VER_SZ)
#define SB_OFF(buf, ver) (4 * A_VER_SZ + (buf) * (2 * B_VER_SZ) + (ver) * B_VER_SZ)
#define SM_TOT (4 * A_VER_SZ + 4 * B_VER_SZ)   // 61440

// ---------------- scratch (device globals) ----------------
__device__ __align__(16) float g_h  [(size_t)N_NODES * HID];
__device__ __align__(16) float g_out[(size_t)N_NODES * HID];
__device__ __align__(16) __nv_bfloat16 g_Ah[(size_t)N_NODES * IN_DIM];
__device__ __align__(16) __nv_bfloat16 g_Al[(size_t)N_NODES * IN_DIM];
__device__ __align__(16) __nv_bfloat16 g_Bh[(size_t)PAD_N * IN_DIM];  // B^T, K-major
__device__ __align__(16) __nv_bfloat16 g_Bl[(size_t)PAD_N * IN_DIM];
__device__ float g_ssrc  [N_NODES * HEADS];
__device__ float g_sdst  [N_NODES * HEADS];
__device__ float g_rlog  [NUM_REL * HEADS];
__device__ float g_segmax[N_NODES * HEADS];
__device__ float g_denom [N_NODES * HEADS];
__device__ float g_elog  [E_EDGES * HEADS];
__device__ int   g_is64;

// ---------------- helpers ----------------
__device__ __forceinline__ int load_idx(const void* p, int i) {
    if (g_is64) return (int)((const long long*)p)[i];
    return ((const int*)p)[i];
}
__device__ __forceinline__ void atomicMaxFloat(float* addr, float val) {
    if (val >= 0.0f) atomicMax((int*)addr, __float_as_int(val));
    else             atomicMin((unsigned int*)addr, __float_as_uint(val));
}
__device__ __forceinline__ float warp_reduce(float v) {
    #pragma unroll
    for (int o = 16; o > 0; o >>= 1) v += __shfl_down_sync(0xffffffffu, v, o);
    return v;
}
__device__ __forceinline__ uint32_t smem_u32(const void* p) {
    uint32_t a;
    asm("{ .reg .u64 t; cvta.to.shared.u64 t, %1; cvt.u32.u64 %0, t; }" : "=r"(a) : "l"(p));
    return a;
}
__device__ __forceinline__ void cp_async16(uint32_t s, const void* g) {
    asm volatile("cp.async.cg.shared.global [%0], [%1], 16;" :: "r"(s), "l"(g));
}
__device__ __forceinline__ void cp_commit() {
    asm volatile("cp.async.commit_group;" ::: "memory");
}
template<int NN> __device__ __forceinline__ void cp_wait() {
    asm volatile("cp.async.wait_group %0;" :: "n"(NN) : "memory");
}
__device__ __forceinline__ void ldm_x4(uint32_t* r, uint32_t addr) {
    asm volatile("ldmatrix.sync.aligned.m8n8.x4.shared.b16 {%0,%1,%2,%3}, [%4];"
                 : "=r"(r[0]), "=r"(r[1]), "=r"(r[2]), "=r"(r[3]) : "r"(addr));
}
__device__ __forceinline__ void mma16816(float* d, const uint32_t* a, const uint32_t* b) {
    asm volatile(
        "mma.sync.aligned.m16n8k16.row.col.f32.bf16.bf16.f32 "
        "{%0,%1,%2,%3}, {%4,%5,%6,%7}, {%8,%9}, {%0,%1,%2,%3};"
        : "+f"(d[0]), "+f"(d[1]), "+f"(d[2]), "+f"(d[3])
        : "r"(a[0]), "r"(a[1]), "r"(a[2]), "r"(a[3]), "r"(b[0]), "r"(b[1]));
}

// ---------------- 0) dtype detection ----------------
__global__ void detect_dtype_kernel(const void* edge_index) {
    if (threadIdx.x == 0 && blockIdx.x == 0) {
        const long long* p = (const long long*)edge_index;
        int ok = 1;
        for (int i = 0; i < 64; i++) {
            long long v = p[i];
            if (v < 0 || v >= N_NODES) { ok = 0; break; }
        }
        g_is64 = ok;
    }
}

// ---------------- 1a) split A into bf16 hi/lo ----------------
__global__ void split_a_kernel(const float* __restrict__ A) {
    size_t i4 = (size_t)blockIdx.x * blockDim.x + threadIdx.x;
    size_t tot = (size_t)N_NODES * IN_DIM / 4;
    if (i4 >= tot) return;
    float4 a = ((const float4*)A)[i4];
    __nv_bfloat16 hx = __float2bfloat16(a.x), hy = __float2bfloat16(a.y);
    __nv_bfloat16 hz = __float2bfloat16(a.z), hw = __float2bfloat16(a.w);
    __nv_bfloat16 lx = __float2bfloat16(a.x - __bfloat162float(hx));
    __nv_bfloat16 ly = __float2bfloat16(a.y - __bfloat162float(hy));
    __nv_bfloat16 lz = __float2bfloat16(a.z - __bfloat162float(hz));
    __nv_bfloat16 lw = __float2bfloat16(a.w - __bfloat162float(hw));
    __nv_bfloat162* ph = (__nv_bfloat162*)g_Ah;
    __nv_bfloat162* pl = (__nv_bfloat162*)g_Al;
    ph[i4 * 2]     = __nv_bfloat162(hx, hy);
    ph[i4 * 2 + 1] = __nv_bfloat162(hz, hw);
    pl[i4 * 2]     = __nv_bfloat162(lx, ly);
    pl[i4 * 2 + 1] = __nv_bfloat162(lz, lw);
}

// ---------------- 1b) split + transpose B: W[K,HID] -> Bt[PAD_N,K] ----------------
__global__ void split_b_kernel(const float* __restrict__ Wm) {
    size_t i = (size_t)blockIdx.x * blockDim.x + threadIdx.x;
    size_t tot = (size_t)PAD_N * IN_DIM;
    if (i >= tot) return;
    int n = (int)(i / IN_DIM);
    int k = (int)(i % IN_DIM);
    float v = (n < HID) ? Wm[(size_t)k * HID + n] : 0.0f;
    __nv_bfloat16 hi = __float2bfloat16(v);
    __nv_bfloat16 lo = __float2bfloat16(v - __bfloat162float(hi));
    g_Bh[i] = hi;
    g_Bl[i] = lo;
}

// ---------------- 2) init ----------------
__global__ void init_kernel() {
    const size_t tid = (size_t)blockIdx.x * blockDim.x + threadIdx.x;
    const size_t nthreads = (size_t)gridDim.x * blockDim.x;
    float4* o4 = (float4*)g_out;
    const size_t tot4 = (size_t)N_NODES * HID / 4;
    for (size_t i = tid; i < tot4; i += nthreads)
        o4[i] = make_float4(0.f, 0.f, 0.f, 0.f);
    if (tid < (size_t)N_NODES * HEADS) {
        g_segmax[tid] = -FLT_MAX;
        g_denom[tid]  = 0.0f;
    }
}

// ---------------- 3) HMMA GEMM: g_h = A @ W via bf16 split ----------------
__global__ void __launch_bounds__(256) gemm_mma_kernel() {
    extern __shared__ char smem[];
    const uint32_t sbase = smem_u32(smem);
    const int t = threadIdx.x;
    const int lane = t & 31;
    const int warp = t >> 5;
    const int wm = warp >> 1;          // 0..3 -> 32-row slice
    const int wn = warp & 1;           // 0..1 -> 32-col slice
    const int n0 = blockIdx.x * BN;    // N fastest -> A reuse in L2
    const int row0 = blockIdx.y * BM;

    float acc[2][4][4];
    #pragma unroll
    for (int mi = 0; mi < 2; mi++)
        #pragma unroll
        for (int nj = 0; nj < 4; nj++)
            #pragma unroll
            for (int q = 0; q < 4; q++) acc[mi][nj][q] = 0.0f;

    auto load_chunk = [&](int c, int buf) {
        // A: 128 rows x 32 k, 4x16B per row, both versions
        #pragma unroll
        for (int i = 0; i < 2; i++) {
            int lin = i * 256 + t;         // 0..511
            int r = lin >> 2, seg = lin & 3;
            int gr = row0 + r; if (gr > N_NODES - 1) gr = N_NODES - 1;
            size_t go = (size_t)gr * IN_DIM + c * BK + seg * 8;
            uint32_t so = (uint32_t)(r * A_STRIDE + seg * 16);
            cp_async16(sbase + SA_OFF(buf, 0) + so, g_Ah + go);
            cp_async16(sbase + SA_OFF(buf, 1) + so, g_Al + go);
        }
        // B: 64 rows x 32 k
        {
            int r = t >> 2, seg = t & 3;   // r 0..63
            size_t go = (size_t)(n0 + r) * IN_DIM + c * BK + seg * 8;
            uint32_t so = (uint32_t)(r * A_STRIDE + seg * 16);
            cp_async16(sbase + SB_OFF(buf, 0) + so, g_Bh + go);
            cp_async16(sbase + SB_OFF(buf, 1) + so, g_Bl + go);
        }
        cp_commit();
    };

    load_chunk(0, 0);
    load_chunk(1, 1);

    for (int c = 0; c < NCHUNK; c++) {
        if (c == NCHUNK - 1) cp_wait<0>(); else cp_wait<1>();
        __syncthreads();
        const int buf = c & 1;

        #pragma unroll
        for (int k16 = 0; k16 < BK; k16 += 16) {
            // A fragments: rows wm*32 + mi*16, ldmatrix.x4 non-trans
            uint32_t af[2][2][4];   // [ver][mi][4]
            #pragma unroll
            for (int ver = 0; ver < 2; ver++)
                #pragma unroll
                for (int mi = 0; mi < 2; mi++) {
                    int r = wm * 32 + mi * 16 + (lane & 7) + ((lane >> 3) & 1) * 8;
                    int colB = (k16 + (lane >> 4) * 8) * 2;
                    ldm_x4(af[ver][mi], sbase + SA_OFF(buf, ver) + r * A_STRIDE + colB);
                }
            // B fragments: n = wn*32 + pair*16 .. ; x4 = two n8 tiles (klo,khi)
            uint32_t bf[2][4][2];   // [ver][nj][2]
            #pragma unroll
            for (int ver = 0; ver < 2; ver++)
                #pragma unroll
                for (int pr = 0; pr < 2; pr++) {
                    uint32_t r4[4];
                    int n = wn * 32 + pr * 16 + ((lane >> 4) & 1) * 8 + (lane & 7);
                    int colB = (k16 + ((lane >> 3) & 1) * 8) * 2;
                    ldm_x4(r4, sbase + SB_OFF(buf, ver) + n * A_STRIDE + colB);
                    bf[ver][pr * 2 + 0][0] = r4[0]; bf[ver][pr * 2 + 0][1] = r4[1];
                    bf[ver][pr * 2 + 1][0] = r4[2]; bf[ver][pr * 2 + 1][1] = r4[3];
                }
            // three-pass accumulate: AhBh + AhBl + AlBh
            #pragma unroll
            for (int mi = 0; mi < 2; mi++)
                #pragma unroll
                for (int nj = 0; nj < 4; nj++) {
                    mma16816(acc[mi][nj], af[0][mi], bf[0][nj]);
                    mma16816(acc[mi][nj], af[0][mi], bf[1][nj]);
                    mma16816(acc[mi][nj], af[1][mi], bf[0][nj]);
                }
        }
        __syncthreads();
        if (c + 2 < NCHUNK) load_chunk(c + 2, buf);
    }

    // epilogue: acc[mi][nj]: c0=D[r][col], c1=D[r][col+1], c2=D[r+8][col], c3
    #pragma unroll
    for (int mi = 0; mi < 2; mi++)
        #pragma unroll
        for (int nj = 0; nj < 4; nj++) {
            int tileN = n0 + wn * 32 + nj * 8;
            if (tileN >= HID) continue;
            int col = tileN + 2 * (lane & 3);
            int r0 = row0 + wm * 32 + mi * 16 + (lane >> 2);
            if (r0 < N_NODES)
                *(float2*)(g_h + (size_t)r0 * HID + col) =
                    make_float2(acc[mi][nj][0], acc[mi][nj][1]);
            int r1 = r0 + 8;
            if (r1 < N_NODES)
                *(float2*)(g_h + (size_t)r1 * HID + col) =
                    make_float2(acc[mi][nj][2], acc[mi][nj][3]);
        }
}

// ---------------- 4) per-node attention projections ----------------
__global__ void node_logits_kernel(const float* __restrict__ a_src,
                                   const float* __restrict__ a_dst) {
    int wid  = (blockIdx.x * blockDim.x + threadIdx.x) >> 5;
    int lane = threadIdx.x & 31;
    if (wid >= N_NODES * HEADS) return;
    int n = wid >> 2, h = wid & 3;
    const float* hp = g_h + (size_t)n * HID + h * OUT_DIM;
    const float* as = a_src + h * OUT_DIM;
    const float* ad = a_dst + h * OUT_DIM;
    float ss = 0.f, sd = 0.f;
    for (int d = lane; d < OUT_DIM; d += 32) {
        float v = hp[d];
        ss = fmaf(v, as[d], ss);
        sd = fmaf(v, ad[d], sd);
    }
    ss = warp_reduce(ss);
    sd = warp_reduce(sd);
    if (lane == 0) { g_ssrc[wid] = ss; g_sdst[wid] = sd; }
}

__global__ void rel_logits_kernel(const float* __restrict__ rel_feat,
                                  const float* __restrict__ a_rel) {
    int wid  = (blockIdx.x * blockDim.x + threadIdx.x) >> 5;
    int lane = threadIdx.x & 31;
    if (wid >= NUM_REL * HEADS) return;
    int r = wid >> 2, h = wid & 3;
    const float* rp = rel_feat + (size_t)r * HID + h * OUT_DIM;
    const float* ar = a_rel + h * OUT_DIM;
    float s = 0.f;
    for (int d = lane; d < OUT_DIM; d += 32) s = fmaf(rp[d], ar[d], s);
    s = warp_reduce(s);
    if (lane == 0) g_rlog[wid] = s;
}

// ---------------- 5) per-edge logits + segment max ----------------
__global__ void edge_max_kernel(const void* __restrict__ ei,
                                const void* __restrict__ et) {
    int idx = blockIdx.x * blockDim.x + threadIdx.x;
    if (idx >= E_EDGES * HEADS) return;
    int e = idx >> 2, h = idx & 3;
    int s = load_idx(ei, e);
    int d = load_idx(ei, E_EDGES + e);
    int r = load_idx(et, e);
    float x = g_ssrc[s * 4 + h] + g_sdst[d * 4 + h] + g_rlog[r * 4 + h];
    x = (x >= 0.f) ? x : NEG_SLOPE * x;
    g_elog[idx] = x;
    atomicMaxFloat(&g_segmax[d * 4 + h], x);
}

// ---------------- 6) exp + segment sum ----------------
__global__ void edge_exp_kernel(const void* __restrict__ ei) {
    int idx = blockIdx.x * blockDim.x + threadIdx.x;
    if (idx >= E_EDGES * HEADS) return;
    int e = idx >> 2, h = idx & 3;
    int d = load_idx(ei, E_EDGES + e);
    float ev = expf(g_elog[idx] - g_segmax[d * 4 + h]);
    g_elog[idx] = ev;
    atomicAdd(&g_denom[d * 4 + h], ev);
}

// ---------------- 7) weighted scatter-aggregate ----------------
__global__ void edge_agg_kernel(const void* __restrict__ ei) {
    int wid  = (blockIdx.x * blockDim.x + threadIdx.x) >> 5;
    int lane = threadIdx.x & 31;
    if (wid >= E_EDGES) return;
    int s = load_idx(ei, wid);
    int d = load_idx(ei, E_EDGES + wid);
    float alpha[HEADS];
    #pragma unroll
    for (int h = 0; h < HEADS; h++)
        alpha[h] = g_elog[wid * 4 + h] / g_denom[d * 4 + h];
    const float4* hs = (const float4*)(g_h + (size_t)s * HID);
    float4*       op = (float4*)(g_out + (size_t)d * HID);
    for (int c = lane; c < HID / 4; c += 32) {
        float a = alpha[c / 50];
        float4 v = hs[c];
        float4 w = make_float4(v.x * a, v.y * a, v.z * a, v.w * a);
        atomicAdd(op + c, w);
    }
}

// ---------------- 8) DistMult ----------------
__global__ void distmult_kernel(const float* __restrict__ bias,
                                const float* __restrict__ rel_emb,
                                const void* __restrict__ si,
                                const void* __restrict__ ri,
                                const void* __restrict__ di,
                                float* __restrict__ out) {
    int wid  = (blockIdx.x * blockDim.x + threadIdx.x) >> 5;
    int lane = threadIdx.x & 31;
    if (wid >= BATCH) return;
    int s = load_idx(si, wid);
    int r = load_idx(ri, wid);
    int d = load_idx(di, wid);
    const float* ps = g_out + (size_t)s * HID;
    const float* pd = g_out + (size_t)d * HID;
    const float* pr = rel_emb + (size_t)r * HID;
    float acc = 0.f;
    for (int k = lane; k < HID; k += 32) {
        float b = bias[k];
        acc = fmaf((ps[k] + b) * pr[k], (pd[k] + b), acc);
    }
    acc = warp_reduce(acc);
    if (lane == 0) out[wid] = acc;
}

// ---------------- launch ----------------
extern "C" void kernel_launch(void* const* d_in, const int* in_sizes, int n_in,
                              void* d_out, int out_size) {
    const float* node_emb   = (const float*)d_in[0];
    const float* Wm         = (const float*)d_in[1];
    const float* bias       = (const float*)d_in[2];
    const float* a_src      = (const float*)d_in[3];
    const float* a_dst      = (const float*)d_in[4];
    const float* a_rel      = (const float*)d_in[5];
    const float* rel_feat   = (const float*)d_in[6];
    const float* rel_emb    = (const float*)d_in[7];
    const void*  edge_index = d_in[8];
    const void*  edge_type  = d_in[9];
    const void*  src_ids    = d_in[10];
    const void*  rel_ids    = d_in[11];
    const void*  dst_ids    = d_in[12];
    float* out = (float*)d_out;

    cudaFuncSetAttribute(gemm_mma_kernel,
                         cudaFuncAttributeMaxDynamicSharedMemorySize, SM_TOT);

    detect_dtype_kernel<<<1, 32>>>(edge_index);

    {
        size_t tot4 = (size_t)N_NODES * IN_DIM / 4;
        split_a_kernel<<<(unsigned)((tot4 + 255) / 256), 256>>>(node_emb);
        size_t totb = (size_t)PAD_N * IN_DIM;
        split_b_kernel<<<(unsigned)((totb + 255) / 256), 256>>>(Wm);
    }

    init_kernel<<<(N_NODES * HEADS + 255) / 256, 256>>>();

    dim3 ggrid(NT_N, NT_M);
    gemm_mma_kernel<<<ggrid, 256, SM_TOT>>>();

    node_logits_kernel<<<(N_NODES * HEADS * 32 + 255) / 256, 256>>>(a_src, a_dst);
    rel_logits_kernel<<<(NUM_REL * HEADS * 32 + 255) / 256, 256>>>(rel_feat, a_rel);

    edge_max_kernel<<<(E_EDGES * HEADS + 255) / 256, 256>>>(edge_index, edge_type);
    edge_exp_kernel<<<(E_EDGES * HEADS + 255) / 256, 256>>>(edge_index);
    edge_agg_kernel<<<(E_EDGES * 32 + 255) / 256, 256>>>(edge_index);

    distmult_kernel<<<(BATCH * 32 + 255) / 256, 256>>>(bias, rel_emb,
                                                       src_ids, rel_ids, dst_ids, out);
}